// round 2
// baseline (speedup 1.0000x reference)
#include <cuda_runtime.h>
#include <math.h>

// Problem constants: B=4, S=4096, D=512
#define BB 4
#define SS 4096
#define DD 512
#define MT (BB * SS)  // 16384 flattened rows

// ---------------------------------------------------------------------------
// Scratch in __device__ globals (no allocation allowed in kernel_launch).
// ---------------------------------------------------------------------------
__device__ float g_K[(size_t)MT * DD];        // 33.5 MB
__device__ float g_Q[(size_t)MT * DD];        // 33.5 MB
__device__ float g_V[(size_t)MT * DD];        // 33.5 MB
__device__ float g_E[(size_t)BB * SS * SS];   // 268 MB : exp(qk/512)
__device__ float g_Z[MT];                     // column sums of E (per batch, per e)
__device__ float g_invZ[MT];
__device__ float g_rowsum[MT];

// ---------------------------------------------------------------------------
// Shared GEMM structure: C[m,n] = sum_k A[m,k] * B[n,k]  (both K-major),
// 128x128 block tile, BK=16, 256 threads, 8x8 per-thread microtile.
// A/B staged transposed in smem (As[k][m]) so the inner loop does LDS.128.
// ---------------------------------------------------------------------------

// ---- Kernel 1: K/Q/V = xs @ W^T + b, selected by blockIdx.z ----
__global__ __launch_bounds__(256, 2) void kqv_kernel(
    const float* __restrict__ X,
    const float* __restrict__ Wk_, const float* __restrict__ bk_,
    const float* __restrict__ Wq_, const float* __restrict__ bq_,
    const float* __restrict__ Wv_, const float* __restrict__ bv_)
{
    const float* W; const float* bias; float* C;
    if (blockIdx.z == 0)      { W = Wk_; bias = bk_; C = g_K; }
    else if (blockIdx.z == 1) { W = Wq_; bias = bq_; C = g_Q; }
    else                      { W = Wv_; bias = bv_; C = g_V; }

    __shared__ float As[16][132];
    __shared__ float Bs[16][132];
    const int tid = threadIdx.x;
    const int tx = tid & 15, ty = tid >> 4;
    const int m0 = blockIdx.y * 128, n0 = blockIdx.x * 128;

    float acc[8][8];
#pragma unroll
    for (int i = 0; i < 8; i++)
#pragma unroll
        for (int j = 0; j < 8; j++) acc[i][j] = 0.f;

    for (int k0 = 0; k0 < DD; k0 += 16) {
#pragma unroll
        for (int t = 0; t < 2; t++) {
            int f = tid + t * 256;
            int row = f >> 2;
            int c4  = (f & 3) << 2;
            float4 va = *(const float4*)(X + (size_t)(m0 + row) * DD + k0 + c4);
            As[c4 + 0][row] = va.x; As[c4 + 1][row] = va.y;
            As[c4 + 2][row] = va.z; As[c4 + 3][row] = va.w;
            float4 vb = *(const float4*)(W + (size_t)(n0 + row) * DD + k0 + c4);
            Bs[c4 + 0][row] = vb.x; Bs[c4 + 1][row] = vb.y;
            Bs[c4 + 2][row] = vb.z; Bs[c4 + 3][row] = vb.w;
        }
        __syncthreads();
#pragma unroll
        for (int k = 0; k < 16; k++) {
            float a[8], b[8];
            *(float4*)(a)     = *(const float4*)&As[k][ty * 8];
            *(float4*)(a + 4) = *(const float4*)&As[k][ty * 8 + 4];
            *(float4*)(b)     = *(const float4*)&Bs[k][tx * 8];
            *(float4*)(b + 4) = *(const float4*)&Bs[k][tx * 8 + 4];
#pragma unroll
            for (int i = 0; i < 8; i++)
#pragma unroll
                for (int j = 0; j < 8; j++)
                    acc[i][j] = fmaf(a[i], b[j], acc[i][j]);
        }
        __syncthreads();
    }

    float bvec[8];
#pragma unroll
    for (int j = 0; j < 8; j++) bvec[j] = bias[n0 + tx * 8 + j];
#pragma unroll
    for (int i = 0; i < 8; i++) {
        size_t off = (size_t)(m0 + ty * 8 + i) * DD + n0 + tx * 8;
        float4 o0 = make_float4(acc[i][0] + bvec[0], acc[i][1] + bvec[1],
                                acc[i][2] + bvec[2], acc[i][3] + bvec[3]);
        float4 o1 = make_float4(acc[i][4] + bvec[4], acc[i][5] + bvec[5],
                                acc[i][6] + bvec[6], acc[i][7] + bvec[7]);
        *(float4*)(C + off)     = o0;
        *(float4*)(C + off + 4) = o1;
    }
}

// ---- Kernel 2: E = exp((K @ Q^T)/512), plus column-sum partials into g_Z ----
__global__ __launch_bounds__(256, 2) void qk_kernel()
{
    const int bidx = blockIdx.z;
    const float* __restrict__ A  = g_K + (size_t)bidx * SS * DD;
    const float* __restrict__ Bm = g_Q + (size_t)bidx * SS * DD;
    float* __restrict__ C  = g_E + (size_t)bidx * SS * SS;
    float* __restrict__ Zb = g_Z + bidx * SS;

    __shared__ float As[16][132];
    __shared__ float Bs[16][132];
    __shared__ float sZ[128];
    const int tid = threadIdx.x;
    const int tx = tid & 15, ty = tid >> 4;
    const int m0 = blockIdx.y * 128, n0 = blockIdx.x * 128;

    if (tid < 128) sZ[tid] = 0.f;  // covered by the first __syncthreads below

    float acc[8][8];
#pragma unroll
    for (int i = 0; i < 8; i++)
#pragma unroll
        for (int j = 0; j < 8; j++) acc[i][j] = 0.f;

    for (int k0 = 0; k0 < DD; k0 += 16) {
#pragma unroll
        for (int t = 0; t < 2; t++) {
            int f = tid + t * 256;
            int row = f >> 2;
            int c4  = (f & 3) << 2;
            float4 va = *(const float4*)(A + (size_t)(m0 + row) * DD + k0 + c4);
            As[c4 + 0][row] = va.x; As[c4 + 1][row] = va.y;
            As[c4 + 2][row] = va.z; As[c4 + 3][row] = va.w;
            float4 vb = *(const float4*)(Bm + (size_t)(n0 + row) * DD + k0 + c4);
            Bs[c4 + 0][row] = vb.x; Bs[c4 + 1][row] = vb.y;
            Bs[c4 + 2][row] = vb.z; Bs[c4 + 3][row] = vb.w;
        }
        __syncthreads();
#pragma unroll
        for (int k = 0; k < 16; k++) {
            float a[8], b[8];
            *(float4*)(a)     = *(const float4*)&As[k][ty * 8];
            *(float4*)(a + 4) = *(const float4*)&As[k][ty * 8 + 4];
            *(float4*)(b)     = *(const float4*)&Bs[k][tx * 8];
            *(float4*)(b + 4) = *(const float4*)&Bs[k][tx * 8 + 4];
#pragma unroll
            for (int i = 0; i < 8; i++)
#pragma unroll
                for (int j = 0; j < 8; j++)
                    acc[i][j] = fmaf(a[i], b[j], acc[i][j]);
        }
        __syncthreads();
    }

    // Epilogue: E = exp(acc/512). qk/512 is bounded (~|0.3| max) so no max-
    // subtraction is needed for softmax stability.
    const float inv512 = 0.001953125f;
#pragma unroll
    for (int i = 0; i < 8; i++)
#pragma unroll
        for (int j = 0; j < 8; j++)
            acc[i][j] = __expf(acc[i][j] * inv512);

#pragma unroll
    for (int i = 0; i < 8; i++) {
        size_t off = (size_t)(m0 + ty * 8 + i) * SS + n0 + tx * 8;
        *(float4*)(C + off)     = make_float4(acc[i][0], acc[i][1], acc[i][2], acc[i][3]);
        *(float4*)(C + off + 4) = make_float4(acc[i][4], acc[i][5], acc[i][6], acc[i][7]);
    }

    // Column (over s) partial sums -> shared -> one global atomic per column.
#pragma unroll
    for (int j = 0; j < 8; j++) {
        float s = acc[0][j] + acc[1][j] + acc[2][j] + acc[3][j]
                + acc[4][j] + acc[5][j] + acc[6][j] + acc[7][j];
        atomicAdd(&sZ[tx * 8 + j], s);
    }
    __syncthreads();
    if (tid < 128) atomicAdd(&Zb[n0 + tid], sZ[tid]);
}

// ---- Kernel 3 helpers ----
__global__ void zeroZ_kernel() {
    int i = blockIdx.x * 256 + threadIdx.x;
    if (i < MT) g_Z[i] = 0.f;
}
__global__ void invZ_kernel() {
    int i = blockIdx.x * 256 + threadIdx.x;
    if (i < MT) g_invZ[i] = 1.0f / g_Z[i];
}

// ---- Kernel 3: rowsum[m] = sum_e E[m,e] * invZ[b,e] ----
__global__ __launch_bounds__(256) void rowsum_kernel()
{
    const int m = blockIdx.x;          // 0..16383
    const int b = m >> 12;             // m / 4096
    const float* __restrict__ Er = g_E + (size_t)m * SS;
    const float* __restrict__ iz = g_invZ + b * SS;
    float s = 0.f;
#pragma unroll
    for (int it = 0; it < 4; it++) {
        int e = (threadIdx.x + it * 256) * 4;
        float4 ev = *(const float4*)(Er + e);
        float4 zv = *(const float4*)(iz + e);
        s += ev.x * zv.x + ev.y * zv.y + ev.z * zv.z + ev.w * zv.w;
    }
#pragma unroll
    for (int o = 16; o > 0; o >>= 1) s += __shfl_xor_sync(0xffffffffu, s, o);
    __shared__ float red[8];
    if ((threadIdx.x & 31) == 0) red[threadIdx.x >> 5] = s;
    __syncthreads();
    if (threadIdx.x == 0) {
        float t = 0.f;
#pragma unroll
        for (int w = 0; w < 8; w++) t += red[w];
        g_rowsum[m] = t;
    }
}

// ---- Kernel 4: out = tanh((rowsum .* V) @ Wl^T + bl) ----
__global__ __launch_bounds__(256, 2) void out_kernel(
    const float* __restrict__ Wl_, const float* __restrict__ bl_,
    float* __restrict__ out)
{
    __shared__ float As[16][132];
    __shared__ float Bs[16][132];
    const int tid = threadIdx.x;
    const int tx = tid & 15, ty = tid >> 4;
    const int m0 = blockIdx.y * 128, n0 = blockIdx.x * 128;

    float acc[8][8];
#pragma unroll
    for (int i = 0; i < 8; i++)
#pragma unroll
        for (int j = 0; j < 8; j++) acc[i][j] = 0.f;

    for (int k0 = 0; k0 < DD; k0 += 16) {
#pragma unroll
        for (int t = 0; t < 2; t++) {
            int f = tid + t * 256;
            int row = f >> 2;
            int c4  = (f & 3) << 2;
            float rs = g_rowsum[m0 + row];
            float4 va = *(const float4*)(g_V + (size_t)(m0 + row) * DD + k0 + c4);
            As[c4 + 0][row] = va.x * rs; As[c4 + 1][row] = va.y * rs;
            As[c4 + 2][row] = va.z * rs; As[c4 + 3][row] = va.w * rs;
            float4 vb = *(const float4*)(Wl_ + (size_t)(n0 + row) * DD + k0 + c4);
            Bs[c4 + 0][row] = vb.x; Bs[c4 + 1][row] = vb.y;
            Bs[c4 + 2][row] = vb.z; Bs[c4 + 3][row] = vb.w;
        }
        __syncthreads();
#pragma unroll
        for (int k = 0; k < 16; k++) {
            float a[8], b[8];
            *(float4*)(a)     = *(const float4*)&As[k][ty * 8];
            *(float4*)(a + 4) = *(const float4*)&As[k][ty * 8 + 4];
            *(float4*)(b)     = *(const float4*)&Bs[k][tx * 8];
            *(float4*)(b + 4) = *(const float4*)&Bs[k][tx * 8 + 4];
#pragma unroll
            for (int i = 0; i < 8; i++)
#pragma unroll
                for (int j = 0; j < 8; j++)
                    acc[i][j] = fmaf(a[i], b[j], acc[i][j]);
        }
        __syncthreads();
    }

    float bvec[8];
#pragma unroll
    for (int j = 0; j < 8; j++) bvec[j] = bl_[n0 + tx * 8 + j];
#pragma unroll
    for (int i = 0; i < 8; i++) {
        size_t off = (size_t)(m0 + ty * 8 + i) * DD + n0 + tx * 8;
        float4 o0 = make_float4(tanhf(acc[i][0] + bvec[0]), tanhf(acc[i][1] + bvec[1]),
                                tanhf(acc[i][2] + bvec[2]), tanhf(acc[i][3] + bvec[3]));
        float4 o1 = make_float4(tanhf(acc[i][4] + bvec[4]), tanhf(acc[i][5] + bvec[5]),
                                tanhf(acc[i][6] + bvec[6]), tanhf(acc[i][7] + bvec[7]));
        *(float4*)(out + off)     = o0;
        *(float4*)(out + off + 4) = o1;
    }
}

// ---------------------------------------------------------------------------
extern "C" void kernel_launch(void* const* d_in, const int* in_sizes, int n_in,
                              void* d_out, int out_size)
{
    const float* xs = (const float*)d_in[0];
    const float* Wk = (const float*)d_in[1];
    const float* bk = (const float*)d_in[2];
    const float* Wq = (const float*)d_in[3];
    const float* bq = (const float*)d_in[4];
    const float* Wv = (const float*)d_in[5];
    const float* bv = (const float*)d_in[6];
    const float* Wl = (const float*)d_in[7];
    const float* bl = (const float*)d_in[8];
    float* out = (float*)d_out;
    (void)in_sizes; (void)n_in; (void)out_size;

    zeroZ_kernel<<<MT / 256, 256>>>();
    kqv_kernel<<<dim3(DD / 128, MT / 128, 3), 256>>>(xs, Wk, bk, Wq, bq, Wv, bv);
    qk_kernel<<<dim3(SS / 128, SS / 128, BB), 256>>>();
    invZ_kernel<<<MT / 256, 256>>>();
    rowsum_kernel<<<MT, 256>>>();
    out_kernel<<<dim3(DD / 128, MT / 128), 256>>>(Wl, bl, out);
}

// round 4
// speedup vs baseline: 3.6985x; 3.6985x over previous
#include <cuda_runtime.h>
#include <math.h>
#include <stdint.h>

// Problem constants: B=4, S=4096, D=512
#define BB 4
#define SS 4096
#define DD 512
#define MT (BB * SS)  // 16384

// GEMM tiling
#define BK 32
#define NCH (DD / BK)           // 16 k-chunks
#define STAGES 3
#define STAGE_A 16384           // A bytes per stage (128 rows x 128B)
#define STAGE_BYTES 32768       // A+B per stage
#define SMEM_MAIN (STAGES * STAGE_BYTES)   // 98304
#define SOUT_STRIDE 132
#define SMEM_TOTAL (SMEM_MAIN + 512)

// ---------------------------------------------------------------------------
// Scratch (__device__ globals; no allocation allowed)
// ---------------------------------------------------------------------------
__device__ float g_X[(size_t)MT * DD];        // tf32-rounded xs
__device__ float g_W[(size_t)4 * DD * DD];    // tf32-rounded Wk,Wq,Wv,Wl
__device__ float g_K[(size_t)MT * DD];
__device__ float g_Q[(size_t)MT * DD];
__device__ float g_V[(size_t)MT * DD];
__device__ float g_E[(size_t)BB * SS * SS];   // exp(qk/512), 268 MB
__device__ float g_Z[MT];                     // column sums -> inverted in place
__device__ float g_rowsum[MT];

// ---------------------------------------------------------------------------
// PTX helpers — ISA-portable only (this toolchain targets compute_103, no 'a';
// tcgen05 does NOT compile). cp.async / ldmatrix / mma.sync are sm_80-era PTX.
// ---------------------------------------------------------------------------
static __device__ __forceinline__ uint32_t smem_u32(const void* p) {
    uint32_t a;
    asm("{ .reg .u64 t; cvta.to.shared.u64 t, %1; cvt.u32.u64 %0, t; }"
        : "=r"(a) : "l"(p));
    return a;
}

#define CP_ASYNC16(sm, gp) \
    asm volatile("cp.async.cg.shared.global [%0], [%1], 16;" :: "r"(sm), "l"(gp) : "memory")
#define CP_COMMIT() asm volatile("cp.async.commit_group;" ::: "memory")
#define CP_WAIT(n)  asm volatile("cp.async.wait_group %0;" :: "n"(n) : "memory")

#define LDSM4(r0, r1, r2, r3, addr) \
    asm volatile("ldmatrix.sync.aligned.m8n8.x4.shared.b16 {%0,%1,%2,%3}, [%4];" \
                 : "=r"(r0), "=r"(r1), "=r"(r2), "=r"(r3) : "r"(addr))

#define MMA_TF32(c, a, b) \
    asm volatile("mma.sync.aligned.m16n8k8.row.col.f32.tf32.tf32.f32 " \
                 "{%0,%1,%2,%3},{%4,%5,%6,%7},{%8,%9},{%0,%1,%2,%3};" \
                 : "+f"((c)[0]), "+f"((c)[1]), "+f"((c)[2]), "+f"((c)[3]) \
                 : "r"((a)[0]), "r"((a)[1]), "r"((a)[2]), "r"((a)[3]), \
                   "r"((b)[0]), "r"((b)[1]))

static __device__ __forceinline__ float round_tf32(float x) {
    uint32_t u;
    asm("cvt.rna.tf32.f32 %0, %1;" : "=r"(u) : "f"(x));
    return __uint_as_float(u);
}

// ---------------------------------------------------------------------------
// tf32 mma.sync GEMM: C[m,n] = sum_k A[m,k]*B[n,k], K=512, block tile 128x128,
// BK=32, 3-stage cp.async pipeline, 8 warps, warp tile 64x32 (2x4 layout).
// MODE 0: C = round_tf32(acc + bias[n])            (K/Q/V projections)
// MODE 1: C = exp(acc/512), column-sum partials into g_Z  (qk)
// MODE 2: C = tanh(acc + bias[n])                  (final output)
// ---------------------------------------------------------------------------
template <int MODE>
__global__ __launch_bounds__(256) void gemm_mma(
    const float* __restrict__ Ag, const float* __restrict__ Bg,
    const float* __restrict__ bias, float* __restrict__ Cg,
    int ldc, size_t sA, size_t sB, size_t sC)
{
    extern __shared__ char smem[];
    const uint32_t sbase = smem_u32(smem);
    float* sOut = (float*)smem;                 // reused after mainloop
    float* sZ   = (float*)(smem + SMEM_MAIN);
    const int tid = threadIdx.x;
    const int lane = tid & 31, wid = tid >> 5;
    const int wm = wid & 1, wn = wid >> 1;      // warp grid 2(M) x 4(N)
    const int m0 = blockIdx.y * 128, n0 = blockIdx.x * 128;
    const int z = blockIdx.z;

    const char* Ab = (const char*)(Ag + (size_t)z * sA);
    const char* Bb = (const char*)(Bg + (size_t)z * sB);
    float* C = Cg + (size_t)z * sC;

    if (MODE == 1 && tid < 128) sZ[tid] = 0.f;

    // --- cp.async staging offsets: 4 granules of 16B per matrix per chunk ---
    // granule g: row = g>>3 (8x16B = 128B per row), colbytes = (g&7)*16.
    // SW128 swizzle on 128B rows.
    uint32_t so[4], gA[4], gB[4];
#pragma unroll
    for (int i = 0; i < 4; i++) {
        int g = tid + 256 * i;
        int row = g >> 3, cb = (g & 7) * 16;
        uint32_t raw = (uint32_t)row * 128u + (uint32_t)cb;
        so[i] = raw ^ ((raw >> 3) & 0x70u);
        gA[i] = (uint32_t)((m0 + row) * DD) * 4u + (uint32_t)cb;
        gB[i] = (uint32_t)((n0 + row) * DD) * 4u + (uint32_t)cb;
    }

    // --- ldmatrix per-lane addressing ---
    // A frag (m16k8): mats {rows+0,c0},{rows+8,c0},{rows+0,c0+4},{rows+8,c0+4}
    //   lane row-in-tile = ((lane>>3)&1)*8 + (lane&7); col sel = ((lane>>4)&1)*16B
    // B frags (two n8k8 per x4): mats {n+0,c0},{n+0,c0+4},{n+8,c0},{n+8,c0+4}
    //   lane row = ((lane>>4)&1)*8 + (lane&7); col sel = ((lane>>3)&1)*16B
    const int arow = ((lane >> 3) & 1) * 8 + (lane & 7);
    const int brow = ((lane >> 4) & 1) * 8 + (lane & 7);
    uint32_t aOff[4], bOff[2];
#pragma unroll
    for (int f = 0; f < 4; f++) aOff[f] = (uint32_t)((wm * 64 + f * 16 + arow) * 128);
#pragma unroll
    for (int j = 0; j < 2; j++) bOff[j] = (uint32_t)((wn * 32 + j * 16 + brow) * 128);
    const uint32_t swx = ((uint32_t)(lane & 7)) << 4;  // swizzle XOR (row%8)<<4
    const uint32_t cAsel = (uint32_t)(((lane >> 4) & 1) * 16);
    const uint32_t cBsel = (uint32_t)(((lane >> 3) & 1) * 16);

    float acc[4][4][4];
#pragma unroll
    for (int f = 0; f < 4; f++)
#pragma unroll
        for (int nf = 0; nf < 4; nf++)
#pragma unroll
            for (int r = 0; r < 4; r++) acc[f][nf][r] = 0.f;

    auto load_chunk = [&](int c, int s) {
        uint32_t stA = sbase + (uint32_t)s * STAGE_BYTES;
        uint32_t stB = stA + STAGE_A;
        uint32_t ko = (uint32_t)c * 128u;  // BK=32 floats = 128B
#pragma unroll
        for (int i = 0; i < 4; i++) {
            CP_ASYNC16(stA + so[i], Ab + gA[i] + ko);
            CP_ASYNC16(stB + so[i], Bb + gB[i] + ko);
        }
    };

    auto compute = [&](int s) {
        uint32_t stA = sbase + (uint32_t)s * STAGE_BYTES;
        uint32_t stB = stA + STAGE_A;
#pragma unroll
        for (int ks = 0; ks < 4; ks++) {
            uint32_t a[4][4], b[2][4];
            uint32_t cA = (uint32_t)ks * 32u + cAsel;
            uint32_t cB = (uint32_t)ks * 32u + cBsel;
#pragma unroll
            for (int f = 0; f < 4; f++)
                LDSM4(a[f][0], a[f][1], a[f][2], a[f][3],
                      stA + aOff[f] + (cA ^ swx));
#pragma unroll
            for (int j = 0; j < 2; j++)
                LDSM4(b[j][0], b[j][1], b[j][2], b[j][3],
                      stB + bOff[j] + (cB ^ swx));
#pragma unroll
            for (int f = 0; f < 4; f++)
#pragma unroll
                for (int nf = 0; nf < 4; nf++)
                    MMA_TF32(acc[f][nf], a[f], &b[nf >> 1][(nf & 1) * 2]);
        }
    };

    // --- pipeline: preload 2 stages, then wait/compute/load ---
    load_chunk(0, 0); CP_COMMIT();
    load_chunk(1, 1); CP_COMMIT();
    for (int c = 0; c < NCH; c++) {
        CP_WAIT(1);          // chunk c resident
        __syncthreads();
        compute(c % 3);
        __syncthreads();     // all reads of stage (c%3) done before rewrite
        if (c + 2 < NCH) load_chunk(c + 2, (c + 2) % 3);
        CP_COMMIT();
    }

    // --- epilogue: acc -> smem (stride 132), then coalesced transform-store ---
    // acc frag (m16n8): c0=(r, 2q) c1=(r, 2q+1) c2=(r+8, 2q) c3=(r+8, 2q+1),
    // r = lane>>2, q = lane&3.
#pragma unroll
    for (int f = 0; f < 4; f++) {
        int row = wm * 64 + f * 16 + (lane >> 2);
#pragma unroll
        for (int nf = 0; nf < 4; nf++) {
            int col = wn * 32 + nf * 8 + 2 * (lane & 3);
            *(float2*)&sOut[row * SOUT_STRIDE + col] =
                make_float2(acc[f][nf][0], acc[f][nf][1]);
            *(float2*)&sOut[(row + 8) * SOUT_STRIDE + col] =
                make_float2(acc[f][nf][2], acc[f][nf][3]);
        }
    }
    __syncthreads();

    const int col = (tid & 31) * 4;
    float csum0 = 0.f, csum1 = 0.f, csum2 = 0.f, csum3 = 0.f;
    float4 bv = make_float4(0.f, 0.f, 0.f, 0.f);
    if (MODE != 1) bv = *(const float4*)&bias[n0 + col];
    const float inv512 = 0.001953125f;

#pragma unroll
    for (int i = 0; i < 16; i++) {
        int row = (tid >> 5) + i * 8;
        float4 v = *(float4*)&sOut[row * SOUT_STRIDE + col];
        if (MODE == 1) {
            v.x = __expf(v.x * inv512); v.y = __expf(v.y * inv512);
            v.z = __expf(v.z * inv512); v.w = __expf(v.w * inv512);
            csum0 += v.x; csum1 += v.y; csum2 += v.z; csum3 += v.w;
        } else if (MODE == 0) {
            v.x = round_tf32(v.x + bv.x); v.y = round_tf32(v.y + bv.y);
            v.z = round_tf32(v.z + bv.z); v.w = round_tf32(v.w + bv.w);
        } else {
            v.x = tanhf(v.x + bv.x); v.y = tanhf(v.y + bv.y);
            v.z = tanhf(v.z + bv.z); v.w = tanhf(v.w + bv.w);
        }
        *(float4*)&C[(size_t)(m0 + row) * ldc + n0 + col] = v;
    }

    if (MODE == 1) {
        atomicAdd(&sZ[col + 0], csum0);
        atomicAdd(&sZ[col + 1], csum1);
        atomicAdd(&sZ[col + 2], csum2);
        atomicAdd(&sZ[col + 3], csum3);
        __syncthreads();
        if (tid < 128)
            atomicAdd(&g_Z[(size_t)z * SS + n0 + tid], sZ[tid]);
    }
}

// ---------------------------------------------------------------------------
// Small helper kernels
// ---------------------------------------------------------------------------
// Round all GEMM inputs to tf32 (unbiased rna) once. blockIdx.y selects tensor.
__global__ __launch_bounds__(256) void roundAll_kernel(
    const float* __restrict__ xs, const float* __restrict__ Wk,
    const float* __restrict__ Wq, const float* __restrict__ Wv,
    const float* __restrict__ Wl)
{
    const int t = blockIdx.x * 256 + threadIdx.x;
    const int which = blockIdx.y;
    const float4* src; float4* dst; int n4;
    if (which == 0)      { src = (const float4*)xs; dst = (float4*)g_X;            n4 = MT * DD / 4; }
    else if (which == 1) { src = (const float4*)Wk; dst = (float4*)(g_W + 0 * (size_t)DD * DD); n4 = DD * DD / 4; }
    else if (which == 2) { src = (const float4*)Wq; dst = (float4*)(g_W + 1 * (size_t)DD * DD); n4 = DD * DD / 4; }
    else if (which == 3) { src = (const float4*)Wv; dst = (float4*)(g_W + 2 * (size_t)DD * DD); n4 = DD * DD / 4; }
    else                 { src = (const float4*)Wl; dst = (float4*)(g_W + 3 * (size_t)DD * DD); n4 = DD * DD / 4; }
    if (t < n4) {
        float4 v = src[t];
        v.x = round_tf32(v.x); v.y = round_tf32(v.y);
        v.z = round_tf32(v.z); v.w = round_tf32(v.w);
        dst[t] = v;
    }
}

__global__ void zeroZ_kernel() {
    int i = blockIdx.x * 256 + threadIdx.x;
    if (i < MT) g_Z[i] = 0.f;
}
__global__ void invZ_kernel() {
    int i = blockIdx.x * 256 + threadIdx.x;
    if (i < MT) g_Z[i] = 1.0f / g_Z[i];
}

// rowsum[m] = sum_e E[m,e] * invZ[b,e]
__global__ __launch_bounds__(256) void rowsum_kernel()
{
    const int m = blockIdx.x;
    const int b = m >> 12;
    const float* __restrict__ Er = g_E + (size_t)m * SS;
    const float* __restrict__ iz = g_Z + b * SS;
    float s = 0.f;
#pragma unroll
    for (int it = 0; it < 4; it++) {
        int e = (threadIdx.x + it * 256) * 4;
        float4 ev = *(const float4*)(Er + e);
        float4 zv = *(const float4*)(iz + e);
        s += ev.x * zv.x + ev.y * zv.y + ev.z * zv.z + ev.w * zv.w;
    }
#pragma unroll
    for (int o = 16; o > 0; o >>= 1) s += __shfl_xor_sync(0xffffffffu, s, o);
    __shared__ float red[8];
    if ((threadIdx.x & 31) == 0) red[threadIdx.x >> 5] = s;
    __syncthreads();
    if (threadIdx.x == 0) {
        float t = 0.f;
#pragma unroll
        for (int w = 0; w < 8; w++) t += red[w];
        g_rowsum[m] = t;
    }
}

// V[m,:] = round_tf32(V[m,:] * rowsum[m])  (in place; feeds the final GEMM)
__global__ __launch_bounds__(128) void scaleV_kernel()
{
    const int m = blockIdx.x;
    const float r = g_rowsum[m];
    float4* v = (float4*)(g_V + (size_t)m * DD);
    float4 x = v[threadIdx.x];
    x.x = round_tf32(x.x * r); x.y = round_tf32(x.y * r);
    x.z = round_tf32(x.z * r); x.w = round_tf32(x.w * r);
    v[threadIdx.x] = x;
}

// ---------------------------------------------------------------------------
extern "C" void kernel_launch(void* const* d_in, const int* in_sizes, int n_in,
                              void* d_out, int out_size)
{
    const float* xs = (const float*)d_in[0];
    const float* Wk = (const float*)d_in[1];
    const float* bk = (const float*)d_in[2];
    const float* Wq = (const float*)d_in[3];
    const float* bq = (const float*)d_in[4];
    const float* Wv = (const float*)d_in[5];
    const float* bv = (const float*)d_in[6];
    const float* Wl = (const float*)d_in[7];
    const float* bl = (const float*)d_in[8];
    float* out = (float*)d_out;
    (void)in_sizes; (void)n_in; (void)out_size;

    float *pX, *pW, *pK, *pQ, *pV, *pE;
    cudaGetSymbolAddress((void**)&pX, g_X);
    cudaGetSymbolAddress((void**)&pW, g_W);
    cudaGetSymbolAddress((void**)&pK, g_K);
    cudaGetSymbolAddress((void**)&pQ, g_Q);
    cudaGetSymbolAddress((void**)&pV, g_V);
    cudaGetSymbolAddress((void**)&pE, g_E);
    const float* rWk = pW + 0 * (size_t)DD * DD;
    const float* rWq = pW + 1 * (size_t)DD * DD;
    const float* rWv = pW + 2 * (size_t)DD * DD;
    const float* rWl = pW + 3 * (size_t)DD * DD;

    cudaFuncSetAttribute(gemm_mma<0>, cudaFuncAttributeMaxDynamicSharedMemorySize, SMEM_TOTAL);
    cudaFuncSetAttribute(gemm_mma<1>, cudaFuncAttributeMaxDynamicSharedMemorySize, SMEM_TOTAL);
    cudaFuncSetAttribute(gemm_mma<2>, cudaFuncAttributeMaxDynamicSharedMemorySize, SMEM_TOTAL);

    const dim3 gSmall(DD / 128, MT / 128, 1);  // (4, 128)
    const dim3 gQK(SS / 128, SS / 128, BB);    // (32, 32, 4)

    // ncu (-s 5 -c 1) captures 0-based launch index 5 -> keep qk there.
    zeroZ_kernel<<<MT / 256, 256>>>();                                            // 0
    roundAll_kernel<<<dim3(MT * DD / 1024, 5), 256>>>(xs, Wk, Wq, Wv, Wl);        // 1
    gemm_mma<0><<<gSmall, 256, SMEM_TOTAL>>>(pX, rWk, bk, pK, DD, 0, 0, 0);       // 2: K
    gemm_mma<0><<<gSmall, 256, SMEM_TOTAL>>>(pX, rWq, bq, pQ, DD, 0, 0, 0);       // 3: Q
    gemm_mma<0><<<gSmall, 256, SMEM_TOTAL>>>(pX, rWv, bv, pV, DD, 0, 0, 0);       // 4: V
    gemm_mma<1><<<gQK, 256, SMEM_TOTAL>>>(pK, pQ, nullptr, pE, SS,                // 5: qk
                                          (size_t)SS * DD, (size_t)SS * DD,
                                          (size_t)SS * SS);
    invZ_kernel<<<MT / 256, 256>>>();                                             // 6
    rowsum_kernel<<<MT, 256>>>();                                                 // 7
    scaleV_kernel<<<MT, 128>>>();                                                 // 8
    gemm_mma<2><<<gSmall, 256, SMEM_TOTAL>>>(pV, rWl, bl, out, DD, 0, 0, 0);      // 9
}

// round 5
// speedup vs baseline: 4.0644x; 1.0989x over previous
#include <cuda_runtime.h>
#include <cuda_bf16.h>
#include <math.h>
#include <stdint.h>

// Problem constants: B=4, S=4096, D=512
#define BB 4
#define SS 4096
#define DD 512
#define MT (BB * SS)  // 16384

// GEMM tiling
#define BK 32
#define NCH (DD / BK)           // 16 k-chunks
#define STAGES 3
#define STAGE_A 16384           // A bytes per stage (128 rows x 128B)
#define STAGE_BYTES 32768       // A+B per stage
#define SMEM_MAIN (STAGES * STAGE_BYTES)   // 98304
#define SOUT_STRIDE 132
#define SMEM_TOTAL (SMEM_MAIN + 512)

// ---------------------------------------------------------------------------
// Scratch (__device__ globals; no allocation allowed)
// ---------------------------------------------------------------------------
__device__ float g_X[(size_t)MT * DD];           // tf32-rounded xs
__device__ float g_W[(size_t)4 * DD * DD];       // tf32-rounded Wk,Wq,Wv,Wl
__device__ float g_KQV[(size_t)3 * MT * DD];     // K | Q | V (tf32-rounded)
__device__ __nv_bfloat16 g_E[(size_t)BB * SS * SS];  // exp(qk/512), bf16, 134 MB
__device__ float g_Z[MT];                        // column sums -> inverted in place
__device__ float g_rowsum[MT];

// ---------------------------------------------------------------------------
// PTX helpers — ISA-portable only (toolchain targets compute_103 WITHOUT 'a';
// tcgen05 does not compile). cp.async / ldmatrix / mma.sync are fine.
// ---------------------------------------------------------------------------
static __device__ __forceinline__ uint32_t smem_u32(const void* p) {
    uint32_t a;
    asm("{ .reg .u64 t; cvta.to.shared.u64 t, %1; cvt.u32.u64 %0, t; }"
        : "=r"(a) : "l"(p));
    return a;
}

#define CP_ASYNC16(sm, gp) \
    asm volatile("cp.async.cg.shared.global [%0], [%1], 16;" :: "r"(sm), "l"(gp) : "memory")
#define CP_COMMIT() asm volatile("cp.async.commit_group;" ::: "memory")
#define CP_WAIT(n)  asm volatile("cp.async.wait_group %0;" :: "n"(n) : "memory")

#define LDSM4(r0, r1, r2, r3, addr) \
    asm volatile("ldmatrix.sync.aligned.m8n8.x4.shared.b16 {%0,%1,%2,%3}, [%4];" \
                 : "=r"(r0), "=r"(r1), "=r"(r2), "=r"(r3) : "r"(addr))

#define MMA_TF32(c, a, b) \
    asm volatile("mma.sync.aligned.m16n8k8.row.col.f32.tf32.tf32.f32 " \
                 "{%0,%1,%2,%3},{%4,%5,%6,%7},{%8,%9},{%0,%1,%2,%3};" \
                 : "+f"((c)[0]), "+f"((c)[1]), "+f"((c)[2]), "+f"((c)[3]) \
                 : "r"((a)[0]), "r"((a)[1]), "r"((a)[2]), "r"((a)[3]), \
                   "r"((b)[0]), "r"((b)[1]))

static __device__ __forceinline__ float round_tf32(float x) {
    uint32_t u;
    asm("cvt.rna.tf32.f32 %0, %1;" : "=r"(u) : "f"(x));
    return __uint_as_float(u);
}

// ---------------------------------------------------------------------------
// tf32 mma.sync GEMM: C[m,n] = sum_k A[m,k]*B[n,k], K=512, block tile 128x128,
// BK=32, 3-stage cp.async pipeline, 8 warps, warp tile 64x32 (2x4 layout).
// MODE 0: C = round_tf32(acc + bias_z[n])  (fused K/Q/V projections, z=0..2)
// MODE 1: C = bf16(exp(acc/512)), column-sum partials into g_Z  (qk)
// MODE 2: C = tanh(acc + bias[n])          (final output)
// ---------------------------------------------------------------------------
template <int MODE>
__global__ __launch_bounds__(256) void gemm_mma(
    const float* __restrict__ Ag, const float* __restrict__ Bg,
    const float* __restrict__ b0, const float* __restrict__ b1,
    const float* __restrict__ b2, void* __restrict__ Cv,
    int ldc, size_t sA, size_t sB, size_t sC)
{
    extern __shared__ char smem[];
    const uint32_t sbase = smem_u32(smem);
    float* sOut = (float*)smem;                 // reused after mainloop
    float* sZ   = (float*)(smem + SMEM_MAIN);
    const int tid = threadIdx.x;
    const int lane = tid & 31, wid = tid >> 5;
    const int wm = wid & 1, wn = wid >> 1;      // warp grid 2(M) x 4(N)
    const int m0 = blockIdx.y * 128, n0 = blockIdx.x * 128;
    const int z = blockIdx.z;

    const char* Ab = (const char*)(Ag + (size_t)z * sA);
    const char* Bb = (const char*)(Bg + (size_t)z * sB);
    const float* bias = (z == 0) ? b0 : ((z == 1) ? b1 : b2);

    if (MODE == 1 && tid < 128) sZ[tid] = 0.f;

    // --- cp.async staging offsets: 4 granules of 16B per matrix per chunk ---
    uint32_t so[4], gA[4], gB[4];
#pragma unroll
    for (int i = 0; i < 4; i++) {
        int g = tid + 256 * i;
        int row = g >> 3, cb = (g & 7) * 16;
        uint32_t raw = (uint32_t)row * 128u + (uint32_t)cb;
        so[i] = raw ^ ((raw >> 3) & 0x70u);
        gA[i] = (uint32_t)((m0 + row) * DD) * 4u + (uint32_t)cb;
        gB[i] = (uint32_t)((n0 + row) * DD) * 4u + (uint32_t)cb;
    }

    // --- ldmatrix per-lane addressing (tf32 fragments via b16 x4 loads) ---
    const int arow = ((lane >> 3) & 1) * 8 + (lane & 7);
    const int brow = ((lane >> 4) & 1) * 8 + (lane & 7);
    uint32_t aOff[4], bOff[2];
#pragma unroll
    for (int f = 0; f < 4; f++) aOff[f] = (uint32_t)((wm * 64 + f * 16 + arow) * 128);
#pragma unroll
    for (int j = 0; j < 2; j++) bOff[j] = (uint32_t)((wn * 32 + j * 16 + brow) * 128);
    const uint32_t swx = ((uint32_t)(lane & 7)) << 4;
    const uint32_t cAsel = (uint32_t)(((lane >> 4) & 1) * 16);
    const uint32_t cBsel = (uint32_t)(((lane >> 3) & 1) * 16);

    float acc[4][4][4];
#pragma unroll
    for (int f = 0; f < 4; f++)
#pragma unroll
        for (int nf = 0; nf < 4; nf++)
#pragma unroll
            for (int r = 0; r < 4; r++) acc[f][nf][r] = 0.f;

    auto load_chunk = [&](int c, int s) {
        uint32_t stA = sbase + (uint32_t)s * STAGE_BYTES;
        uint32_t stB = stA + STAGE_A;
        uint32_t ko = (uint32_t)c * 128u;
#pragma unroll
        for (int i = 0; i < 4; i++) {
            CP_ASYNC16(stA + so[i], Ab + gA[i] + ko);
            CP_ASYNC16(stB + so[i], Bb + gB[i] + ko);
        }
    };

    auto compute = [&](int s) {
        uint32_t stA = sbase + (uint32_t)s * STAGE_BYTES;
        uint32_t stB = stA + STAGE_A;
#pragma unroll
        for (int ks = 0; ks < 4; ks++) {
            uint32_t a[4][4], b[2][4];
            uint32_t cA = (uint32_t)ks * 32u + cAsel;
            uint32_t cB = (uint32_t)ks * 32u + cBsel;
#pragma unroll
            for (int f = 0; f < 4; f++)
                LDSM4(a[f][0], a[f][1], a[f][2], a[f][3],
                      stA + aOff[f] + (cA ^ swx));
#pragma unroll
            for (int j = 0; j < 2; j++)
                LDSM4(b[j][0], b[j][1], b[j][2], b[j][3],
                      stB + bOff[j] + (cB ^ swx));
#pragma unroll
            for (int f = 0; f < 4; f++)
#pragma unroll
                for (int nf = 0; nf < 4; nf++)
                    MMA_TF32(acc[f][nf], a[f], &b[nf >> 1][(nf & 1) * 2]);
        }
    };

    // --- pipeline: ONE barrier per chunk; loads issued BEFORE compute so
    // cp.async overlaps the MMA burst. Safe: load(c+2) writes stage
    // (c+2)%3 == (c-1)%3, whose last read (compute(c-1)) is ordered by this
    // iteration's barrier. ---
    load_chunk(0, 0); CP_COMMIT();
    load_chunk(1, 1); CP_COMMIT();
    for (int c = 0; c < NCH; c++) {
        CP_WAIT(1);          // chunk c resident
        __syncthreads();
        if (c + 2 < NCH) load_chunk(c + 2, (c + 2) % 3);
        CP_COMMIT();
        compute(c % 3);
    }
    __syncthreads();         // all compute done before sOut overwrites stage 0

    // --- epilogue: acc -> smem (stride 132), then coalesced transform-store ---
#pragma unroll
    for (int f = 0; f < 4; f++) {
        int row = wm * 64 + f * 16 + (lane >> 2);
#pragma unroll
        for (int nf = 0; nf < 4; nf++) {
            int col = wn * 32 + nf * 8 + 2 * (lane & 3);
            *(float2*)&sOut[row * SOUT_STRIDE + col] =
                make_float2(acc[f][nf][0], acc[f][nf][1]);
            *(float2*)&sOut[(row + 8) * SOUT_STRIDE + col] =
                make_float2(acc[f][nf][2], acc[f][nf][3]);
        }
    }
    __syncthreads();

    const int col = (tid & 31) * 4;
    float csum0 = 0.f, csum1 = 0.f, csum2 = 0.f, csum3 = 0.f;
    float4 bv = make_float4(0.f, 0.f, 0.f, 0.f);
    if (MODE != 1) bv = *(const float4*)&bias[n0 + col];
    const float inv512 = 0.001953125f;

#pragma unroll
    for (int i = 0; i < 16; i++) {
        int row = (tid >> 5) + i * 8;
        float4 v = *(float4*)&sOut[row * SOUT_STRIDE + col];
        if (MODE == 1) {
            v.x = __expf(v.x * inv512); v.y = __expf(v.y * inv512);
            v.z = __expf(v.z * inv512); v.w = __expf(v.w * inv512);
            csum0 += v.x; csum1 += v.y; csum2 += v.z; csum3 += v.w;
            __nv_bfloat16* Cb = (__nv_bfloat16*)Cv + (size_t)z * sC;
            __nv_bfloat162 p0 = __floats2bfloat162_rn(v.x, v.y);
            __nv_bfloat162 p1 = __floats2bfloat162_rn(v.z, v.w);
            uint2 pk = make_uint2(*(uint32_t*)&p0, *(uint32_t*)&p1);
            *(uint2*)&Cb[(size_t)(m0 + row) * ldc + n0 + col] = pk;
        } else {
            float* Cf = (float*)Cv + (size_t)z * sC;
            if (MODE == 0) {
                v.x = round_tf32(v.x + bv.x); v.y = round_tf32(v.y + bv.y);
                v.z = round_tf32(v.z + bv.z); v.w = round_tf32(v.w + bv.w);
            } else {
                v.x = tanhf(v.x + bv.x); v.y = tanhf(v.y + bv.y);
                v.z = tanhf(v.z + bv.z); v.w = tanhf(v.w + bv.w);
            }
            *(float4*)&Cf[(size_t)(m0 + row) * ldc + n0 + col] = v;
        }
    }

    if (MODE == 1) {
        atomicAdd(&sZ[col + 0], csum0);
        atomicAdd(&sZ[col + 1], csum1);
        atomicAdd(&sZ[col + 2], csum2);
        atomicAdd(&sZ[col + 3], csum3);
        __syncthreads();
        if (tid < 128)
            atomicAdd(&g_Z[(size_t)z * SS + n0 + tid], sZ[tid]);
    }
}

// ---------------------------------------------------------------------------
// Small helper kernels
// ---------------------------------------------------------------------------
__global__ __launch_bounds__(256) void roundAll_kernel(
    const float* __restrict__ xs, const float* __restrict__ Wk,
    const float* __restrict__ Wq, const float* __restrict__ Wv,
    const float* __restrict__ Wl)
{
    const int t = blockIdx.x * 256 + threadIdx.x;
    const int which = blockIdx.y;
    const float4* src; float4* dst; int n4;
    if (which == 0)      { src = (const float4*)xs; dst = (float4*)g_X;            n4 = MT * DD / 4; }
    else if (which == 1) { src = (const float4*)Wk; dst = (float4*)(g_W + 0 * (size_t)DD * DD); n4 = DD * DD / 4; }
    else if (which == 2) { src = (const float4*)Wq; dst = (float4*)(g_W + 1 * (size_t)DD * DD); n4 = DD * DD / 4; }
    else if (which == 3) { src = (const float4*)Wv; dst = (float4*)(g_W + 2 * (size_t)DD * DD); n4 = DD * DD / 4; }
    else                 { src = (const float4*)Wl; dst = (float4*)(g_W + 3 * (size_t)DD * DD); n4 = DD * DD / 4; }
    if (t < n4) {
        float4 v = src[t];
        v.x = round_tf32(v.x); v.y = round_tf32(v.y);
        v.z = round_tf32(v.z); v.w = round_tf32(v.w);
        dst[t] = v;
    }
}

__global__ void zeroZ_kernel() {
    int i = blockIdx.x * 256 + threadIdx.x;
    if (i < MT) g_Z[i] = 0.f;
}
__global__ void invZ_kernel() {
    int i = blockIdx.x * 256 + threadIdx.x;
    if (i < MT) g_Z[i] = 1.0f / g_Z[i];
}

// rowsum[m] = sum_e E[m,e]*invZ[b,e]  (E in bf16), then scale V row in place.
__global__ __launch_bounds__(256) void rowsum_scale_kernel()
{
    const int m = blockIdx.x;
    const int b = m >> 12;
    const __nv_bfloat16* __restrict__ Er = g_E + (size_t)m * SS;
    const float* __restrict__ iz = g_Z + b * SS;
    float s = 0.f;
#pragma unroll
    for (int it = 0; it < 2; it++) {
        int e = (threadIdx.x + it * 256) * 8;
        uint4 raw = *(const uint4*)(Er + e);
        float4 z0 = *(const float4*)(iz + e);
        float4 z1 = *(const float4*)(iz + e + 4);
        float2 p0 = __bfloat1622float2(*(__nv_bfloat162*)&raw.x);
        float2 p1 = __bfloat1622float2(*(__nv_bfloat162*)&raw.y);
        float2 p2 = __bfloat1622float2(*(__nv_bfloat162*)&raw.z);
        float2 p3 = __bfloat1622float2(*(__nv_bfloat162*)&raw.w);
        s += p0.x * z0.x + p0.y * z0.y + p1.x * z0.z + p1.y * z0.w
           + p2.x * z1.x + p2.y * z1.y + p3.x * z1.z + p3.y * z1.w;
    }
#pragma unroll
    for (int o = 16; o > 0; o >>= 1) s += __shfl_xor_sync(0xffffffffu, s, o);
    __shared__ float red[8];
    __shared__ float rbc;
    if ((threadIdx.x & 31) == 0) red[threadIdx.x >> 5] = s;
    __syncthreads();
    if (threadIdx.x == 0) {
        float t = 0.f;
#pragma unroll
        for (int w = 0; w < 8; w++) t += red[w];
        g_rowsum[m] = t;
        rbc = t;
    }
    __syncthreads();
    const float r = rbc;
    // scale V row (V = g_KQV slot 2), tf32-round for the final GEMM
    float4* v = (float4*)(g_KQV + 2 * (size_t)MT * DD + (size_t)m * DD);
    if (threadIdx.x < 128) {
        float4 x = v[threadIdx.x];
        x.x = round_tf32(x.x * r); x.y = round_tf32(x.y * r);
        x.z = round_tf32(x.z * r); x.w = round_tf32(x.w * r);
        v[threadIdx.x] = x;
    }
}

// ---------------------------------------------------------------------------
extern "C" void kernel_launch(void* const* d_in, const int* in_sizes, int n_in,
                              void* d_out, int out_size)
{
    const float* xs = (const float*)d_in[0];
    const float* Wk = (const float*)d_in[1];
    const float* bk = (const float*)d_in[2];
    const float* Wq = (const float*)d_in[3];
    const float* bq = (const float*)d_in[4];
    const float* Wv = (const float*)d_in[5];
    const float* bv = (const float*)d_in[6];
    const float* Wl = (const float*)d_in[7];
    const float* bl = (const float*)d_in[8];
    float* out = (float*)d_out;
    (void)in_sizes; (void)n_in; (void)out_size;

    float *pX, *pW, *pKQV;
    __nv_bfloat16* pE;
    cudaGetSymbolAddress((void**)&pX, g_X);
    cudaGetSymbolAddress((void**)&pW, g_W);
    cudaGetSymbolAddress((void**)&pKQV, g_KQV);
    cudaGetSymbolAddress((void**)&pE, g_E);
    const float* rWl = pW + 3 * (size_t)DD * DD;
    float* pK = pKQV;
    float* pQ = pKQV + (size_t)MT * DD;
    float* pV = pKQV + 2 * (size_t)MT * DD;

    cudaFuncSetAttribute(gemm_mma<0>, cudaFuncAttributeMaxDynamicSharedMemorySize, SMEM_TOTAL);
    cudaFuncSetAttribute(gemm_mma<1>, cudaFuncAttributeMaxDynamicSharedMemorySize, SMEM_TOTAL);
    cudaFuncSetAttribute(gemm_mma<2>, cudaFuncAttributeMaxDynamicSharedMemorySize, SMEM_TOTAL);

    const dim3 gKQV(DD / 128, MT / 128, 3);   // (4, 128, 3) fused projections
    const dim3 gQK(SS / 128, SS / 128, BB);   // (32, 32, 4)
    const dim3 gOut(DD / 128, MT / 128, 1);

    zeroZ_kernel<<<MT / 256, 256>>>();
    roundAll_kernel<<<dim3(MT * DD / 1024, 5), 256>>>(xs, Wk, Wq, Wv, Wl);
    // fused K/Q/V projections: A=X (sA=0), B=g_W+z*DD*DD, C=g_KQV+z*MT*DD
    gemm_mma<0><<<gKQV, 256, SMEM_TOTAL>>>(pX, pW, bk, bq, bv, pKQV, DD,
                                           0, (size_t)DD * DD, (size_t)MT * DD);
    // qk: A=K, B=Q per batch; C=E (bf16) + column sums into g_Z
    gemm_mma<1><<<gQK, 256, SMEM_TOTAL>>>(pK, pQ, nullptr, nullptr, nullptr, pE, SS,
                                          (size_t)SS * DD, (size_t)SS * DD,
                                          (size_t)SS * SS);
    invZ_kernel<<<MT / 256, 256>>>();
    rowsum_scale_kernel<<<MT, 256>>>();
    // out = tanh((rowsum.*V) @ Wl^T + bl)
    gemm_mma<2><<<gOut, 256, SMEM_TOTAL>>>(pV, rWl, bl, bl, bl, out, DD,
                                           0, 0, 0);
}

// round 7
// speedup vs baseline: 5.3790x; 1.3235x over previous
#include <cuda_runtime.h>
#include <cuda_bf16.h>
#include <math.h>
#include <stdint.h>

// Problem constants: B=4, S=4096, D=512
#define BB 4
#define SS 4096
#define DD 512
#define MT (BB * SS)  // 16384

// GEMM tiling (both variants stage 128 rows x 128B per matrix per stage)
#define STAGES 3
#define STAGE_A 16384
#define STAGE_BYTES 32768
#define SMEM_MAIN (STAGES * STAGE_BYTES)   // 98304
#define SOUT_STRIDE 132
#define SMEM_TOTAL (SMEM_MAIN + 512)
#define NCH_TF32 16   // K=512 / 32 floats per 128B row-chunk
#define NCH_BF16 8    // K=512 / 64 bf16  per 128B row-chunk

// ---------------------------------------------------------------------------
// Scratch (__device__ globals; no allocation allowed)
// ---------------------------------------------------------------------------
__device__ float g_X[(size_t)MT * DD];              // tf32-rounded xs
__device__ float g_W[(size_t)4 * DD * DD];          // tf32-rounded Wk,Wq,Wv,Wl
__device__ __nv_bfloat16 g_KQ[(size_t)2 * MT * DD]; // K | Q in bf16
__device__ float g_V[(size_t)MT * DD];              // V (tf32-rounded)
__device__ __nv_bfloat16 g_E[(size_t)BB * SS * SS]; // exp(qk/512), bf16
__device__ float g_Z[MT];                           // col sums -> inverted in place
__device__ float g_rowsum[MT];

// ---------------------------------------------------------------------------
// PTX helpers — ISA-portable only (toolchain targets compute_103 WITHOUT 'a').
// ---------------------------------------------------------------------------
static __device__ __forceinline__ uint32_t smem_u32(const void* p) {
    uint32_t a;
    asm("{ .reg .u64 t; cvta.to.shared.u64 t, %1; cvt.u32.u64 %0, t; }"
        : "=r"(a) : "l"(p));
    return a;
}

#define CP_ASYNC16(sm, gp) \
    asm volatile("cp.async.cg.shared.global [%0], [%1], 16;" :: "r"(sm), "l"(gp) : "memory")
#define CP_COMMIT() asm volatile("cp.async.commit_group;" ::: "memory")
#define CP_WAIT(n)  asm volatile("cp.async.wait_group %0;" :: "n"(n) : "memory")

#define LDSM4(r0, r1, r2, r3, addr) \
    asm volatile("ldmatrix.sync.aligned.m8n8.x4.shared.b16 {%0,%1,%2,%3}, [%4];" \
                 : "=r"(r0), "=r"(r1), "=r"(r2), "=r"(r3) : "r"(addr))

#define MMA_TF32(c, a, b) \
    asm volatile("mma.sync.aligned.m16n8k8.row.col.f32.tf32.tf32.f32 " \
                 "{%0,%1,%2,%3},{%4,%5,%6,%7},{%8,%9},{%0,%1,%2,%3};" \
                 : "+f"((c)[0]), "+f"((c)[1]), "+f"((c)[2]), "+f"((c)[3]) \
                 : "r"((a)[0]), "r"((a)[1]), "r"((a)[2]), "r"((a)[3]), \
                   "r"((b)[0]), "r"((b)[1]))

#define MMA_BF16(c, a, b) \
    asm volatile("mma.sync.aligned.m16n8k16.row.col.f32.bf16.bf16.f32 " \
                 "{%0,%1,%2,%3},{%4,%5,%6,%7},{%8,%9},{%0,%1,%2,%3};" \
                 : "+f"((c)[0]), "+f"((c)[1]), "+f"((c)[2]), "+f"((c)[3]) \
                 : "r"((a)[0]), "r"((a)[1]), "r"((a)[2]), "r"((a)[3]), \
                   "r"((b)[0]), "r"((b)[1]))

static __device__ __forceinline__ float round_tf32(float x) {
    uint32_t u;
    asm("cvt.rna.tf32.f32 %0, %1;" : "=r"(u) : "f"(x));
    return __uint_as_float(u);
}

// ---------------------------------------------------------------------------
// Shared fragment-addressing setup (identical byte math for tf32-k8 and
// bf16-k16: a "k-step" advances 32B along a 128B row; col selects are 16B).
// ---------------------------------------------------------------------------
struct FragAddr {
    uint32_t so[4];            // cp.async smem offsets (SW128)
    uint32_t aOff[4], bOff[2]; // ldmatrix row-base offsets
    uint32_t swx, cAsel, cBsel;
};

static __device__ __forceinline__ FragAddr make_addr(int tid) {
    FragAddr F;
    const int lane = tid & 31, wid = tid >> 5;
    const int wm = wid & 1, wn = wid >> 1;
#pragma unroll
    for (int i = 0; i < 4; i++) {
        int g = tid + 256 * i;
        int row = g >> 3, cb = (g & 7) * 16;
        uint32_t raw = (uint32_t)row * 128u + (uint32_t)cb;
        F.so[i] = raw ^ ((raw >> 3) & 0x70u);
    }
    const int arow = ((lane >> 3) & 1) * 8 + (lane & 7);
    const int brow = ((lane >> 4) & 1) * 8 + (lane & 7);
#pragma unroll
    for (int f = 0; f < 4; f++) F.aOff[f] = (uint32_t)((wm * 64 + f * 16 + arow) * 128);
#pragma unroll
    for (int j = 0; j < 2; j++) F.bOff[j] = (uint32_t)((wn * 32 + j * 16 + brow) * 128);
    F.swx = ((uint32_t)(lane & 7)) << 4;
    F.cAsel = (uint32_t)(((lane >> 4) & 1) * 16);
    F.cBsel = (uint32_t)(((lane >> 3) & 1) * 16);
    return F;
}

// compute one staged chunk (4 k-steps of 32B each); MMA selected by BF16 flag
template <int BF16>
static __device__ __forceinline__ void compute_stage(
    const FragAddr& F, uint32_t stA, uint32_t stB, float acc[4][4][4])
{
#pragma unroll
    for (int ks = 0; ks < 4; ks++) {
        uint32_t a[4][4], b[2][4];
        uint32_t cA = (uint32_t)ks * 32u + F.cAsel;
        uint32_t cB = (uint32_t)ks * 32u + F.cBsel;
#pragma unroll
        for (int f = 0; f < 4; f++)
            LDSM4(a[f][0], a[f][1], a[f][2], a[f][3],
                  stA + F.aOff[f] + (cA ^ F.swx));
#pragma unroll
        for (int j = 0; j < 2; j++)
            LDSM4(b[j][0], b[j][1], b[j][2], b[j][3],
                  stB + F.bOff[j] + (cB ^ F.swx));
#pragma unroll
        for (int f = 0; f < 4; f++)
#pragma unroll
            for (int nf = 0; nf < 4; nf++) {
                if (BF16) MMA_BF16(acc[f][nf], a[f], &b[nf >> 1][(nf & 1) * 2]);
                else      MMA_TF32(acc[f][nf], a[f], &b[nf >> 1][(nf & 1) * 2]);
            }
    }
}

// acc -> smem scratch (post-mainloop)
static __device__ __forceinline__ void acc_to_smem(
    float* sOut, int lane, int wid, float acc[4][4][4])
{
    const int wm = wid & 1, wn = wid >> 1;
#pragma unroll
    for (int f = 0; f < 4; f++) {
        int row = wm * 64 + f * 16 + (lane >> 2);
#pragma unroll
        for (int nf = 0; nf < 4; nf++) {
            int col = wn * 32 + nf * 8 + 2 * (lane & 3);
            *(float2*)&sOut[row * SOUT_STRIDE + col] =
                make_float2(acc[f][nf][0], acc[f][nf][1]);
            *(float2*)&sOut[(row + 8) * SOUT_STRIDE + col] =
                make_float2(acc[f][nf][2], acc[f][nf][3]);
        }
    }
}

// ---------------------------------------------------------------------------
// tf32 GEMM (projections + output). MODE 0: z=0,1 -> bf16 K/Q; z=2 -> fp32 V.
// MODE 2: out = tanh(acc + bias).
// ---------------------------------------------------------------------------
template <int MODE>
__global__ __launch_bounds__(256) void gemm_tf32(
    const float* __restrict__ Ag, const float* __restrict__ Bg,
    const float* __restrict__ b0, const float* __restrict__ b1,
    const float* __restrict__ b2, float* __restrict__ Cout)
{
    extern __shared__ char smem[];
    const uint32_t sbase = smem_u32(smem);
    float* sOut = (float*)smem;
    const int tid = threadIdx.x;
    const int lane = tid & 31, wid = tid >> 5;
    const int m0 = blockIdx.y * 128, n0 = blockIdx.x * 128;
    const int z = blockIdx.z;

    const char* Ab = (const char*)Ag;                           // X or scaled V
    const char* Bb = (const char*)(Bg + (size_t)z * DD * DD);   // W slice
    const float* bias = (z == 0) ? b0 : ((z == 1) ? b1 : b2);

    FragAddr F = make_addr(tid);
    uint32_t gA[4], gB[4];
#pragma unroll
    for (int i = 0; i < 4; i++) {
        int g = tid + 256 * i;
        int row = g >> 3, cb = (g & 7) * 16;
        gA[i] = (uint32_t)((m0 + row) * DD) * 4u + (uint32_t)cb;
        gB[i] = (uint32_t)((n0 + row) * DD) * 4u + (uint32_t)cb;
    }

    float acc[4][4][4];
#pragma unroll
    for (int f = 0; f < 4; f++)
#pragma unroll
        for (int nf = 0; nf < 4; nf++)
#pragma unroll
            for (int r = 0; r < 4; r++) acc[f][nf][r] = 0.f;

    auto load_chunk = [&](int c, int s) {
        uint32_t stA = sbase + (uint32_t)s * STAGE_BYTES;
        uint32_t stB = stA + STAGE_A;
        uint32_t ko = (uint32_t)c * 128u;
#pragma unroll
        for (int i = 0; i < 4; i++) {
            CP_ASYNC16(stA + F.so[i], Ab + gA[i] + ko);
            CP_ASYNC16(stB + F.so[i], Bb + gB[i] + ko);
        }
    };

    load_chunk(0, 0); CP_COMMIT();
    load_chunk(1, 1); CP_COMMIT();
    for (int c = 0; c < NCH_TF32; c++) {
        CP_WAIT(1);
        __syncthreads();
        if (c + 2 < NCH_TF32) load_chunk(c + 2, (c + 2) % 3);
        CP_COMMIT();
        uint32_t stA = sbase + (uint32_t)(c % 3) * STAGE_BYTES;
        compute_stage<0>(F, stA, stA + STAGE_A, acc);
    }
    __syncthreads();
    acc_to_smem(sOut, lane, wid, acc);
    __syncthreads();

    const int col = (tid & 31) * 4;
    float4 bv = *(const float4*)&bias[n0 + col];
#pragma unroll
    for (int i = 0; i < 16; i++) {
        int row = (tid >> 5) + i * 8;
        float4 v = *(float4*)&sOut[row * SOUT_STRIDE + col];
        v.x += bv.x; v.y += bv.y; v.z += bv.z; v.w += bv.w;
        if (MODE == 0 && z < 2) {
            __nv_bfloat16* Cb = g_KQ + (size_t)z * MT * DD;
            __nv_bfloat162 p0 = __floats2bfloat162_rn(v.x, v.y);
            __nv_bfloat162 p1 = __floats2bfloat162_rn(v.z, v.w);
            uint2 pk = make_uint2(*(uint32_t*)&p0, *(uint32_t*)&p1);
            *(uint2*)&Cb[(size_t)(m0 + row) * DD + n0 + col] = pk;
        } else if (MODE == 0) {
            v.x = round_tf32(v.x); v.y = round_tf32(v.y);
            v.z = round_tf32(v.z); v.w = round_tf32(v.w);
            *(float4*)&g_V[(size_t)(m0 + row) * DD + n0 + col] = v;
        } else {
            v.x = tanhf(v.x); v.y = tanhf(v.y);
            v.z = tanhf(v.z); v.w = tanhf(v.w);
            *(float4*)&Cout[(size_t)(m0 + row) * DD + n0 + col] = v;
        }
    }
}

// ---------------------------------------------------------------------------
// bf16 qk GEMM: E[b] = bf16(exp((K_b @ Q_b^T)/512)), column sums into g_Z.
// K rows are 512 bf16 = 1024B; chunk = 64 k-elems = 128B; 8 chunks.
// ---------------------------------------------------------------------------
__global__ __launch_bounds__(256) void gemm_qk_bf16()
{
    extern __shared__ char smem[];
    const uint32_t sbase = smem_u32(smem);
    float* sOut = (float*)smem;
    float* sZ   = (float*)(smem + SMEM_MAIN);
    const int tid = threadIdx.x;
    const int lane = tid & 31, wid = tid >> 5;
    const int m0 = blockIdx.y * 128, n0 = blockIdx.x * 128;
    const int z = blockIdx.z;

    const char* Ab = (const char*)(g_KQ + (size_t)z * SS * DD);            // K_b
    const char* Bb = (const char*)(g_KQ + (size_t)MT * DD + (size_t)z * SS * DD); // Q_b

    if (tid < 128) sZ[tid] = 0.f;

    FragAddr F = make_addr(tid);
    uint32_t gA[4], gB[4];
#pragma unroll
    for (int i = 0; i < 4; i++) {
        int g = tid + 256 * i;
        int row = g >> 3, cb = (g & 7) * 16;
        gA[i] = (uint32_t)((m0 + row) * DD) * 2u + (uint32_t)cb;  // bf16: 2B/elem
        gB[i] = (uint32_t)((n0 + row) * DD) * 2u + (uint32_t)cb;
    }

    float acc[4][4][4];
#pragma unroll
    for (int f = 0; f < 4; f++)
#pragma unroll
        for (int nf = 0; nf < 4; nf++)
#pragma unroll
            for (int r = 0; r < 4; r++) acc[f][nf][r] = 0.f;

    auto load_chunk = [&](int c, int s) {
        uint32_t stA = sbase + (uint32_t)s * STAGE_BYTES;
        uint32_t stB = stA + STAGE_A;
        uint32_t ko = (uint32_t)c * 128u;
#pragma unroll
        for (int i = 0; i < 4; i++) {
            CP_ASYNC16(stA + F.so[i], Ab + gA[i] + ko);
            CP_ASYNC16(stB + F.so[i], Bb + gB[i] + ko);
        }
    };

    load_chunk(0, 0); CP_COMMIT();
    load_chunk(1, 1); CP_COMMIT();
    for (int c = 0; c < NCH_BF16; c++) {
        CP_WAIT(1);
        __syncthreads();
        if (c + 2 < NCH_BF16) load_chunk(c + 2, (c + 2) % 3);
        CP_COMMIT();
        uint32_t stA = sbase + (uint32_t)(c % 3) * STAGE_BYTES;
        compute_stage<1>(F, stA, stA + STAGE_A, acc);
    }
    __syncthreads();
    acc_to_smem(sOut, lane, wid, acc);
    __syncthreads();

    const int col = (tid & 31) * 4;
    float csum0 = 0.f, csum1 = 0.f, csum2 = 0.f, csum3 = 0.f;
    const float inv512 = 0.001953125f;
    __nv_bfloat16* Cb = g_E + (size_t)z * SS * SS;
#pragma unroll
    for (int i = 0; i < 16; i++) {
        int row = (tid >> 5) + i * 8;
        float4 v = *(float4*)&sOut[row * SOUT_STRIDE + col];
        v.x = __expf(v.x * inv512); v.y = __expf(v.y * inv512);
        v.z = __expf(v.z * inv512); v.w = __expf(v.w * inv512);
        csum0 += v.x; csum1 += v.y; csum2 += v.z; csum3 += v.w;
        __nv_bfloat162 p0 = __floats2bfloat162_rn(v.x, v.y);
        __nv_bfloat162 p1 = __floats2bfloat162_rn(v.z, v.w);
        uint2 pk = make_uint2(*(uint32_t*)&p0, *(uint32_t*)&p1);
        *(uint2*)&Cb[(size_t)(m0 + row) * SS + n0 + col] = pk;
    }
    atomicAdd(&sZ[col + 0], csum0);
    atomicAdd(&sZ[col + 1], csum1);
    atomicAdd(&sZ[col + 2], csum2);
    atomicAdd(&sZ[col + 3], csum3);
    __syncthreads();
    if (tid < 128)
        atomicAdd(&g_Z[(size_t)z * SS + n0 + tid], sZ[tid]);
}

// ---------------------------------------------------------------------------
// Small helper kernels
// ---------------------------------------------------------------------------
__global__ __launch_bounds__(256) void roundAll_kernel(
    const float* __restrict__ xs, const float* __restrict__ Wk,
    const float* __restrict__ Wq, const float* __restrict__ Wv,
    const float* __restrict__ Wl)
{
    const int t = blockIdx.x * 256 + threadIdx.x;
    const int which = blockIdx.y;
    const float4* src; float4* dst; int n4;
    if (which == 0)      { src = (const float4*)xs; dst = (float4*)g_X;            n4 = MT * DD / 4; }
    else if (which == 1) { src = (const float4*)Wk; dst = (float4*)(g_W + 0 * (size_t)DD * DD); n4 = DD * DD / 4; }
    else if (which == 2) { src = (const float4*)Wq; dst = (float4*)(g_W + 1 * (size_t)DD * DD); n4 = DD * DD / 4; }
    else if (which == 3) { src = (const float4*)Wv; dst = (float4*)(g_W + 2 * (size_t)DD * DD); n4 = DD * DD / 4; }
    else                 { src = (const float4*)Wl; dst = (float4*)(g_W + 3 * (size_t)DD * DD); n4 = DD * DD / 4; }
    if (t < n4) {
        float4 v = src[t];
        v.x = round_tf32(v.x); v.y = round_tf32(v.y);
        v.z = round_tf32(v.z); v.w = round_tf32(v.w);
        dst[t] = v;
    }
}

__global__ void zeroZ_kernel() {
    int i = blockIdx.x * 256 + threadIdx.x;
    if (i < MT) g_Z[i] = 0.f;
}
__global__ void invZ_kernel() {
    int i = blockIdx.x * 256 + threadIdx.x;
    if (i < MT) g_Z[i] = 1.0f / g_Z[i];
}

// rowsum[m] = sum_e E[m,e]*invZ[b,e] (E bf16), then scale V row in place.
__global__ __launch_bounds__(256) void rowsum_scale_kernel()
{
    const int m = blockIdx.x;
    const int b = m >> 12;
    const __nv_bfloat16* __restrict__ Er = g_E + (size_t)m * SS;
    const float* __restrict__ iz = g_Z + b * SS;
    float s = 0.f;
#pragma unroll
    for (int it = 0; it < 2; it++) {
        int e = (threadIdx.x + it * 256) * 8;
        uint4 raw = *(const uint4*)(Er + e);
        float4 z0 = *(const float4*)(iz + e);
        float4 z1 = *(const float4*)(iz + e + 4);
        float2 p0 = __bfloat1622float2(*(__nv_bfloat162*)&raw.x);
        float2 p1 = __bfloat1622float2(*(__nv_bfloat162*)&raw.y);
        float2 p2 = __bfloat1622float2(*(__nv_bfloat162*)&raw.z);
        float2 p3 = __bfloat1622float2(*(__nv_bfloat162*)&raw.w);
        s += p0.x * z0.x + p0.y * z0.y + p1.x * z0.z + p1.y * z0.w
           + p2.x * z1.x + p2.y * z1.y + p3.x * z1.z + p3.y * z1.w;
    }
#pragma unroll
    for (int o = 16; o > 0; o >>= 1) s += __shfl_xor_sync(0xffffffffu, s, o);
    __shared__ float red[8];
    __shared__ float rbc;
    if ((threadIdx.x & 31) == 0) red[threadIdx.x >> 5] = s;
    __syncthreads();
    if (threadIdx.x == 0) {
        float t = 0.f;
#pragma unroll
        for (int w = 0; w < 8; w++) t += red[w];
        g_rowsum[m] = t;
        rbc = t;
    }
    __syncthreads();
    const float r = rbc;
    float4* v = (float4*)(g_V + (size_t)m * DD);
    if (threadIdx.x < 128) {
        float4 x = v[threadIdx.x];
        x.x = round_tf32(x.x * r); x.y = round_tf32(x.y * r);
        x.z = round_tf32(x.z * r); x.w = round_tf32(x.w * r);
        v[threadIdx.x] = x;
    }
}

// ---------------------------------------------------------------------------
extern "C" void kernel_launch(void* const* d_in, const int* in_sizes, int n_in,
                              void* d_out, int out_size)
{
    const float* xs = (const float*)d_in[0];
    const float* Wk = (const float*)d_in[1];
    const float* bk = (const float*)d_in[2];
    const float* Wq = (const float*)d_in[3];
    const float* bq = (const float*)d_in[4];
    const float* Wv = (const float*)d_in[5];
    const float* bv = (const float*)d_in[6];
    const float* Wl = (const float*)d_in[7];
    const float* bl = (const float*)d_in[8];
    float* out = (float*)d_out;
    (void)in_sizes; (void)n_in; (void)out_size;

    float *pX, *pW, *pV;
    cudaGetSymbolAddress((void**)&pX, g_X);
    cudaGetSymbolAddress((void**)&pW, g_W);
    cudaGetSymbolAddress((void**)&pV, g_V);
    const float* rWl = pW + 3 * (size_t)DD * DD;

    cudaFuncSetAttribute(gemm_tf32<0>, cudaFuncAttributeMaxDynamicSharedMemorySize, SMEM_TOTAL);
    cudaFuncSetAttribute(gemm_tf32<2>, cudaFuncAttributeMaxDynamicSharedMemorySize, SMEM_TOTAL);
    cudaFuncSetAttribute(gemm_qk_bf16, cudaFuncAttributeMaxDynamicSharedMemorySize, SMEM_TOTAL);

    const dim3 gKQV(DD / 128, MT / 128, 3);   // fused K/Q/V projections
    const dim3 gQK(SS / 128, SS / 128, BB);
    const dim3 gOut(DD / 128, MT / 128, 1);

    zeroZ_kernel<<<MT / 256, 256>>>();
    roundAll_kernel<<<dim3(MT * DD / 1024, 5), 256>>>(xs, Wk, Wq, Wv, Wl);
    gemm_tf32<0><<<gKQV, 256, SMEM_TOTAL>>>(pX, pW, bk, bq, bv, nullptr);
    gemm_qk_bf16<<<gQK, 256, SMEM_TOTAL>>>();
    invZ_kernel<<<MT / 256, 256>>>();
    rowsum_scale_kernel<<<MT, 256>>>();
    gemm_tf32<2><<<gOut, 256, SMEM_TOTAL>>>(pV, rWl, bl, bl, bl, out);
}